// round 14
// baseline (speedup 1.0000x reference)
#include <cuda_runtime.h>

#define LSEQ     2048
#define NBATCH   32
#define TOTPAIRS (NBATCH * 1024)   // 32768 global pair indices
#define TPB      256
#define NBLOCKS  296               // 2 * 148: two perfectly balanced waves
#define DTC      0.01f

// log2(e)/sqrt(3): fold softmax scale + e^x->2^x conversion into q
#define QSCALE (1.4426950408889634f / 1.7320508075688772f)

__device__ __forceinline__ float ex2(float x) {
    float r;
    asm("ex2.approx.f32 %0, %1;" : "=f"(r) : "f"(x));
    return r;
}

__global__ void __launch_bounds__(TPB, 2) ac_kernel(
    const float* __restrict__ inputs,
    const float* __restrict__ wi,  const float* __restrict__ bi,
    const float* __restrict__ wo,  const float* __restrict__ bo,
    const float* __restrict__ f1w, const float* __restrict__ f1b,
    const float* __restrict__ f2w, const float* __restrict__ f2b,
    const float* __restrict__ g1w, const float* __restrict__ g1b,
    const float* __restrict__ g2w, const float* __restrict__ g2b,
    const float* __restrict__ m1s, const float* __restrict__ m2s,
    const float* __restrict__ sigma,
    float* __restrict__ out)
{
    // R10's proven 48KB packed tile: {k0,k1,k2,v0} float4 + {v1,v2} float2
    extern __shared__ float smem_raw[];
    float4* sk4 = reinterpret_cast<float4*>(smem_raw);            // [LSEQ]
    float2* sv2 = reinterpret_cast<float2*>(smem_raw + 4 * LSEQ); // [LSEQ]

    const int bid = blockIdx.x;
    const int t = threadIdx.x;
    const int u = t & 127;           // slot within half
    const bool hi_half = (t >= 128);

    const float scl0 = sigma[0] + 1e-5f;
    const float scl1 = sigma[1] + 1e-5f;
    const float inv0 = 1.0f / scl0;
    const float inv1 = 1.0f / scl1;

    // global pair span for this block: equal 110-111 pair spans
    unsigned gp0 = (unsigned)(((unsigned long long)TOTPAIRS * bid) / NBLOCKS);
    const unsigned gp1 = (unsigned)(((unsigned long long)TOTPAIRS * (bid + 1)) / NBLOCKS);

    int prev_batch = -1;

    while (gp0 < gp1) {
        const int batch = (int)(gp0 >> 10);
        const int pbase = (int)(gp0 & 1023u);
        const int cnt   = min((int)(gp1 - gp0), 1024 - pbase);
        const float* __restrict__ xb = inputs + (size_t)batch * LSEQ * 3;

        if (batch != prev_batch) {
            __syncthreads();     // protect prior segment's tile readers
            float wk[9], wv[9], bk[3], bv[3];
            #pragma unroll
            for (int i = 0; i < 9; i++) { wk[i] = wi[9 + i]; wv[i] = wi[18 + i]; }
            #pragma unroll
            for (int i = 0; i < 3; i++) { bk[i] = bi[3 + i]; bv[i] = bi[6 + i]; }
            #pragma unroll
            for (int r = t; r < LSEQ; r += TPB) {
                float x0 = xb[3 * r + 0];
                float x1 = xb[3 * r + 1] * inv0;
                float x2 = xb[3 * r + 2] * inv1;
                float k0 = bk[0] + wk[0] * x0 + wk[1] * x1 + wk[2] * x2;
                float k1 = bk[1] + wk[3] * x0 + wk[4] * x1 + wk[5] * x2;
                float k2 = bk[2] + wk[6] * x0 + wk[7] * x1 + wk[8] * x2;
                float v0 = bv[0] + wv[0] * x0 + wv[1] * x1 + wv[2] * x2;
                float v1 = bv[1] + wv[3] * x0 + wv[4] * x1 + wv[5] * x2;
                float v2 = bv[2] + wv[6] * x0 + wv[7] * x1 + wv[8] * x2;
                sk4[r] = make_float4(k0, k1, k2, v0);
                sv2[r] = make_float2(v1, v2);
            }
            __syncthreads();
            prev_batch = batch;
        }

        if (u < cnt) {
            const int p = pbase + u;
            const int i = hi_half ? (LSEQ - 1 - p) : p;

            // q projection, pre-scaled for ex2
            float q0, q1, q2;
            {
                float x0 = xb[3 * i + 0];
                float x1 = xb[3 * i + 1] * inv0;
                float x2 = xb[3 * i + 2] * inv1;
                q0 = (bi[0] + wi[0] * x0 + wi[1] * x1 + wi[2] * x2) * QSCALE;
                q1 = (bi[1] + wi[3] * x0 + wi[4] * x1 + wi[5] * x2) * QSCALE;
                q2 = (bi[2] + wi[6] * x0 + wi[7] * x1 + wi[8] * x2) * QSCALE;
            }

            // R10's proven scalar loop (broadcast LDS.128 + LDS.64)
            float den = 0.0f, a0 = 0.0f, a1 = 0.0f, a2 = 0.0f;
            #pragma unroll 4
            for (int j = 0; j <= i; j++) {
                float4 kf = sk4[j];
                float s = q0 * kf.x + q1 * kf.y + q2 * kf.z;
                float w = ex2(s);
                float2 vf = sv2[j];
                den += w;
                a0 += w * kf.w;
                a1 += w * vf.x;
                a2 += w * vf.y;
            }
            const float r  = 1.0f / den;
            const float c0 = a0 * r, c1 = a1 * r, c2 = a2 * r;

            // epilogue (params L1-hot)
            float wo10 = wo[3], wo11 = wo[4], wo12 = wo[5];
            float wo20 = wo[6], wo21 = wo[7], wo22 = wo[8];
            float bo1 = bo[1], bo2 = bo[2];
            float G10 = g1w[0], G11 = g1w[1], G12 = g1w[2], G1B = g1b[0];
            float G20 = g2w[0], G21 = g2w[1], G22 = g2w[2], G2B = g2b[0];
            float F10 = f1w[0], F11 = f1w[1], F12 = f1w[2], F1B = f1b[0];
            float F20 = f2w[0], F21 = f2w[1], F22 = f2w[2], F2B = f2b[0];
            float M1 = m1s[0], M2 = m2s[0];

            float s1 = bo1 + wo10 * c0 + wo11 * c1 + wo12 * c2;
            float s2 = bo2 + wo20 * c0 + wo21 * c1 + wo22 * c2;

            float o[8];
            {
                float d1 = (G10 + G11 * s1 + G12 * s2 + G1B) * M1;
                float d2 = (G20 + G21 * s1 + G22 * s2 + G2B) * M2;
                s1 += DTC * d1; s2 += DTC * d2;
                o[0] = s1 * scl0; o[1] = s2 * scl1;
            }
            {
                float d1 = (G10 + G11 * s1 + G12 * s2 + G1B) * M1;
                float d2 = (G20 + G21 * s1 + G22 * s2 + G2B) * M2;
                s1 += DTC * d1; s2 += DTC * d2;
                o[2] = s1 * scl0; o[3] = s2 * scl1;
            }
            {
                float d1 = (G10 + G11 * s1 + G12 * s2 + G1B) * M1;
                float d2 = (G20 + G21 * s1 + G22 * s2 + G2B) * M2;
                s1 += DTC * d1; s2 += DTC * d2;
                o[4] = s1 * scl0; o[5] = s2 * scl1;
            }
            {
                float v1 = (F10 + F11 * s1 + F12 * s2 + F1B) * M1;
                float v2 = (F20 + F21 * s1 + F22 * s2 + F2B) * M2;
                o[6] = (s1 + v1 * DTC) * scl0;
                o[7] = (s2 + v2 * DTC) * scl1;
            }

            float4* op = reinterpret_cast<float4*>(out) + ((size_t)(batch * LSEQ + i)) * 2;
            op[0] = make_float4(o[0], o[1], o[2], o[3]);
            op[1] = make_float4(o[4], o[5], o[6], o[7]);
        }

        gp0 += (unsigned)cnt;
    }
}

extern "C" void kernel_launch(void* const* d_in, const int* in_sizes, int n_in,
                              void* d_out, int out_size)
{
    const float* inputs = (const float*)d_in[1];
    const float* wi     = (const float*)d_in[2];
    const float* bi     = (const float*)d_in[3];
    const float* wo     = (const float*)d_in[4];
    const float* bo     = (const float*)d_in[5];
    const float* f1w    = (const float*)d_in[6];
    const float* f1b    = (const float*)d_in[7];
    const float* f2w    = (const float*)d_in[8];
    const float* f2b    = (const float*)d_in[9];
    const float* g1w    = (const float*)d_in[10];
    const float* g1b    = (const float*)d_in[11];
    const float* g2w    = (const float*)d_in[12];
    const float* g2b    = (const float*)d_in[13];
    const float* m1s    = (const float*)d_in[14];
    const float* m2s    = (const float*)d_in[15];
    const float* sigma  = (const float*)d_in[16];
    float* out = (float*)d_out;

    const int smem = LSEQ * (16 + 8);   // 48 KB packed tile
    cudaFuncSetAttribute(ac_kernel, cudaFuncAttributeMaxDynamicSharedMemorySize, smem);

    ac_kernel<<<NBLOCKS, TPB, smem>>>(inputs, wi, bi, wo, bo,
                                      f1w, f1b, f2w, f2b,
                                      g1w, g1b, g2w, g2b,
                                      m1s, m2s, sigma, out);
}

// round 15
// speedup vs baseline: 1.3452x; 1.3452x over previous
#include <cuda_runtime.h>

#define LSEQ    2048
#define NBATCH  32
#define TPB     128
#define NBLOCKS 592            // 4 * 148: every SM gets exactly 4 blocks
#define DTC     0.01f

// log2(e)/sqrt(3): fold softmax scale + e^x->2^x conversion into q
#define QSCALE (1.4426950408889634f / 1.7320508075688772f)

__device__ __forceinline__ float ex2(float x) {
    float r;
    asm("ex2.approx.f32 %0, %1;" : "=f"(r) : "f"(x));
    return r;
}

__global__ void __launch_bounds__(TPB, 4) ac_kernel(
    const float* __restrict__ inputs,
    const float* __restrict__ wi,  const float* __restrict__ bi,
    const float* __restrict__ wo,  const float* __restrict__ bo,
    const float* __restrict__ f1w, const float* __restrict__ f1b,
    const float* __restrict__ f2w, const float* __restrict__ f2b,
    const float* __restrict__ g1w, const float* __restrict__ g1b,
    const float* __restrict__ g2w, const float* __restrict__ g2b,
    const float* __restrict__ m1s, const float* __restrict__ m2s,
    const float* __restrict__ sigma,
    float* __restrict__ out)
{
    // R10's proven 48KB packed tile: {k0,k1,k2,v0} float4 + {v1,v2} float2
    extern __shared__ float smem_raw[];
    float4* sk4 = reinterpret_cast<float4*>(smem_raw);            // [LSEQ]
    float2* sv2 = reinterpret_cast<float2*>(smem_raw + 4 * LSEQ); // [LSEQ]

    const int bid = blockIdx.x;
    const int t = threadIdx.x;

    // block -> (batch, pair range): 16 batches x 19 blocks + 16 batches x 18 blocks
    int batch, j, nb;
    if (bid < 16 * 19) {
        batch = bid / 19; j = bid - batch * 19; nb = 19;
    } else {
        int rr = bid - 16 * 19;
        int bb = rr / 18;
        batch = 16 + bb; j = rr - bb * 18; nb = 18;
    }
    const int p0  = (1024 * j) / nb;
    const int cnt = (1024 * (j + 1)) / nb - p0;

    const float scl0 = sigma[0] + 1e-5f;
    const float scl1 = sigma[1] + 1e-5f;
    const float inv0 = 1.0f / scl0;
    const float inv1 = 1.0f / scl1;
    const float* __restrict__ xb = inputs + (size_t)batch * LSEQ * 3;

    // ---------------- Phase A: build packed K,V tile (48 KB) ----------------
    {
        float wk[9], wv[9], bk[3], bv[3];
        #pragma unroll
        for (int i = 0; i < 9; i++) { wk[i] = wi[9 + i]; wv[i] = wi[18 + i]; }
        #pragma unroll
        for (int i = 0; i < 3; i++) { bk[i] = bi[3 + i]; bv[i] = bi[6 + i]; }

        for (int r = t; r < LSEQ; r += TPB) {
            float x0 = xb[3 * r + 0];
            float x1 = xb[3 * r + 1] * inv0;
            float x2 = xb[3 * r + 2] * inv1;
            float k0 = bk[0] + wk[0] * x0 + wk[1] * x1 + wk[2] * x2;
            float k1 = bk[1] + wk[3] * x0 + wk[4] * x1 + wk[5] * x2;
            float k2 = bk[2] + wk[6] * x0 + wk[7] * x1 + wk[8] * x2;
            float v0 = bv[0] + wv[0] * x0 + wv[1] * x1 + wv[2] * x2;
            float v1 = bv[1] + wv[3] * x0 + wv[4] * x1 + wv[5] * x2;
            float v2 = bv[2] + wv[6] * x0 + wv[7] * x1 + wv[8] * x2;
            sk4[r] = make_float4(k0, k1, k2, v0);
            sv2[r] = make_float2(v1, v2);
        }
    }
    __syncthreads();

    // ------------- Phase B: one query per thread, mirrored halves -------------
    // threads 0..63: query p0+u (short loops); threads 64..127: 2047-(p0+u) (long)
    const int u = t & 63;
    if (u >= cnt) return;
    const int p = p0 + u;
    const int i = (t < 64) ? p : (LSEQ - 1 - p);

    // q projection (gmem, L1-hot), pre-scaled for ex2
    float q0, q1, q2;
    {
        float x0 = xb[3 * i + 0];
        float x1 = xb[3 * i + 1] * inv0;
        float x2 = xb[3 * i + 2] * inv1;
        q0 = (bi[0] + wi[0] * x0 + wi[1] * x1 + wi[2] * x2) * QSCALE;
        q1 = (bi[1] + wi[3] * x0 + wi[4] * x1 + wi[5] * x2) * QSCALE;
        q2 = (bi[2] + wi[6] * x0 + wi[7] * x1 + wi[8] * x2) * QSCALE;
    }

    // R10's proven scalar loop (broadcast LDS.128 + LDS.64)
    float den = 0.0f, a0 = 0.0f, a1 = 0.0f, a2 = 0.0f;
    #pragma unroll 4
    for (int jj = 0; jj <= i; jj++) {
        float4 kf = sk4[jj];
        float s = q0 * kf.x + q1 * kf.y + q2 * kf.z;
        float w = ex2(s);
        float2 vf = sv2[jj];
        den += w;
        a0 += w * kf.w;
        a1 += w * vf.x;
        a2 += w * vf.y;
    }
    const float r  = 1.0f / den;
    const float c0 = a0 * r, c1 = a1 * r, c2 = a2 * r;

    // -------- epilogue (params L1-hot) --------
    float wo10 = wo[3], wo11 = wo[4], wo12 = wo[5];
    float wo20 = wo[6], wo21 = wo[7], wo22 = wo[8];
    float bo1 = bo[1], bo2 = bo[2];
    float G10 = g1w[0], G11 = g1w[1], G12 = g1w[2], G1B = g1b[0];
    float G20 = g2w[0], G21 = g2w[1], G22 = g2w[2], G2B = g2b[0];
    float F10 = f1w[0], F11 = f1w[1], F12 = f1w[2], F1B = f1b[0];
    float F20 = f2w[0], F21 = f2w[1], F22 = f2w[2], F2B = f2b[0];
    float M1 = m1s[0], M2 = m2s[0];

    float s1 = bo1 + wo10 * c0 + wo11 * c1 + wo12 * c2;
    float s2 = bo2 + wo20 * c0 + wo21 * c1 + wo22 * c2;

    float o[8];
    {
        float d1 = (G10 + G11 * s1 + G12 * s2 + G1B) * M1;
        float d2 = (G20 + G21 * s1 + G22 * s2 + G2B) * M2;
        s1 += DTC * d1; s2 += DTC * d2;
        o[0] = s1 * scl0; o[1] = s2 * scl1;
    }
    {
        float d1 = (G10 + G11 * s1 + G12 * s2 + G1B) * M1;
        float d2 = (G20 + G21 * s1 + G22 * s2 + G2B) * M2;
        s1 += DTC * d1; s2 += DTC * d2;
        o[2] = s1 * scl0; o[3] = s2 * scl1;
    }
    {
        float d1 = (G10 + G11 * s1 + G12 * s2 + G1B) * M1;
        float d2 = (G20 + G21 * s1 + G22 * s2 + G2B) * M2;
        s1 += DTC * d1; s2 += DTC * d2;
        o[4] = s1 * scl0; o[5] = s2 * scl1;
    }
    {
        float v1 = (F10 + F11 * s1 + F12 * s2 + F1B) * M1;
        float v2 = (F20 + F21 * s1 + F22 * s2 + F2B) * M2;
        o[6] = (s1 + v1 * DTC) * scl0;
        o[7] = (s2 + v2 * DTC) * scl1;
    }

    float4* op = reinterpret_cast<float4*>(out) + ((size_t)(batch * LSEQ + i)) * 2;
    op[0] = make_float4(o[0], o[1], o[2], o[3]);
    op[1] = make_float4(o[4], o[5], o[6], o[7]);
}

extern "C" void kernel_launch(void* const* d_in, const int* in_sizes, int n_in,
                              void* d_out, int out_size)
{
    const float* inputs = (const float*)d_in[1];
    const float* wi     = (const float*)d_in[2];
    const float* bi     = (const float*)d_in[3];
    const float* wo     = (const float*)d_in[4];
    const float* bo     = (const float*)d_in[5];
    const float* f1w    = (const float*)d_in[6];
    const float* f1b    = (const float*)d_in[7];
    const float* f2w    = (const float*)d_in[8];
    const float* f2b    = (const float*)d_in[9];
    const float* g1w    = (const float*)d_in[10];
    const float* g1b    = (const float*)d_in[11];
    const float* g2w    = (const float*)d_in[12];
    const float* g2b    = (const float*)d_in[13];
    const float* m1s    = (const float*)d_in[14];
    const float* m2s    = (const float*)d_in[15];
    const float* sigma  = (const float*)d_in[16];
    float* out = (float*)d_out;

    const int smem = LSEQ * (16 + 8);   // 48 KB packed tile
    cudaFuncSetAttribute(ac_kernel, cudaFuncAttributeMaxDynamicSharedMemorySize, smem);

    ac_kernel<<<NBLOCKS, TPB, smem>>>(inputs, wi, bi, wo, bo,
                                      f1w, f1b, f2w, f2b,
                                      g1w, g1b, g2w, g2b,
                                      m1s, m2s, sigma, out);
}